// round 15
// baseline (speedup 1.0000x reference)
#include <cuda_runtime.h>
#include <cuda_fp16.h>

#define HIDDEN    64
#define N_USERS   100000
#define N_MOVIES  50000
#define MOVIE_FEAT 128
#define N_EDGES   2000000
#define N_LABEL   500000

// padded so the single-block scans can read int4 past n without guards
#define NM_PAD (N_MOVIES + 8192)
#define NU_PAD (N_USERS  + 8192)

// ---------------- device scratch (allocation-free rule: __device__ globals) ----------------
// g_deg_* are zero at module load and re-zeroed by scan_kernel after each consumption,
// so every execution of kernel_launch sees them zeroed.
__device__ __align__(16) int g_deg_m[NM_PAD];
__device__ __align__(16) int g_deg_u[NU_PAD];
__device__ __align__(16) int g_off_m[NM_PAD];
__device__ __align__(16) int g_off_u[NU_PAD];
__device__ __align__(16) int g_cur_m[NM_PAD];
__device__ __align__(16) int g_cur_u[NU_PAD];
__device__ int g_csr_m[N_EDGES];   // neighbors (user idx) of each movie, CSR by movie
__device__ int g_csr_u[N_EDGES];   // neighbors (movie idx) of each user, CSR by user
// fp16 node feature buffers with ONE extra row (index N) that is never written:
// __device__ globals are zero-initialized, every writer guards r < n, so row N is
// permanently zero -> aggregation tails load it unconditionally.
__device__ __align__(16) __half g_x16u[(N_USERS  + 1) * HIDDEN];
__device__ __align__(16) __half g_x16m[(N_MOVIES + 1) * HIDDEN];
__device__ __align__(16) __half g_h16u[(N_USERS  + 1) * HIDDEN];
__device__ __align__(16) __half g_h16m[(N_MOVIES + 1) * HIDDEN];
__device__ __align__(16) float g_mu[N_USERS  * HIDDEN];
__device__ __align__(16) float g_mm[N_MOVIES * HIDDEN];

// ---------------- packed f32x2 helpers ----------------
__device__ __forceinline__ unsigned long long pack2(float lo, float hi)
{
    unsigned long long r;
    asm("mov.b64 %0, {%1, %2};" : "=l"(r) : "f"(lo), "f"(hi));
    return r;
}
__device__ __forceinline__ void unpack2(unsigned long long v, float& lo, float& hi)
{
    asm("mov.b64 {%0, %1}, %2;" : "=f"(lo), "=f"(hi) : "l"(v));
}
__device__ __forceinline__ unsigned long long fadd2(unsigned long long a,
                                                    unsigned long long b)
{
    unsigned long long d;
    asm("add.rn.f32x2 %0, %1, %2;" : "=l"(d) : "l"(a), "l"(b));
    return d;
}

#define A_STRIDE 136   // halfs per MMA smem row (128 + 8 pad -> conflict-free frag loads)
#define NB_M_CONST ((N_MOVIES + 127) / 128)          // 391 movie-init blocks
#define GU_BLOCKS  ((N_USERS * 16 + 255) / 256)      // 6250 gather blocks
#define HIST_BLOCKS ((N_EDGES / 4 + 255) / 256)      // 1954 hist/scatter blocks

// ---------------- hist standalone (no smem -> full occupancy) ----------------
__global__ void hist_kernel(const int4* __restrict__ src4, const int4* __restrict__ dst4)
{
    int i = blockIdx.x * blockDim.x + threadIdx.x;
    if (i >= N_EDGES / 4) return;
    int4 s = __ldg(src4 + i), d = __ldg(dst4 + i);
    atomicAdd(&g_deg_u[s.x], 1); atomicAdd(&g_deg_u[s.y], 1);
    atomicAdd(&g_deg_u[s.z], 1); atomicAdd(&g_deg_u[s.w], 1);
    atomicAdd(&g_deg_m[d.x], 1); atomicAdd(&g_deg_m[d.y], 1);
    atomicAdd(&g_deg_m[d.z], 1); atomicAdd(&g_deg_m[d.w], 1);
}

// block 0 scans movie degrees, block 1 scans user degrees; initializes cursors and
// re-zeroes the degree arrays (each thread zeroes its own chunk after reading it).
__global__ __launch_bounds__(1024) void scan_kernel()
{
    int n; int* deg; int* off; int* cur;
    if (blockIdx.x == 0) { n = N_MOVIES; deg = g_deg_m; off = g_off_m; cur = g_cur_m; }
    else                 { n = N_USERS;  deg = g_deg_u; off = g_off_u; cur = g_cur_u; }
    int chunk = ((((n + 1023) >> 10) + 3) & ~3);   // multiple of 4 for int4
    int t = threadIdx.x;
    int start = t * chunk;

    int s = 0;
    for (int i = 0; i < chunk; i += 4) {
        int4 v = *(const int4*)(deg + start + i);
        s += v.x + v.y + v.z + v.w;
    }
    __shared__ int sh[1024];
    sh[t] = s; __syncthreads();
    for (int d = 1; d < 1024; d <<= 1) {
        int v = (t >= d) ? sh[t - d] : 0;
        __syncthreads();
        sh[t] += v;
        __syncthreads();
    }
    int run = t ? sh[t - 1] : 0;
    int4 z = make_int4(0, 0, 0, 0);
    for (int i = 0; i < chunk; i += 4) {
        int4 v = *(const int4*)(deg + start + i);
        int4 o;
        o.x = run; run += v.x;
        o.y = run; run += v.y;
        o.z = run; run += v.z;
        o.w = run; run += v.w;
        *(int4*)(off + start + i) = o;
        *(int4*)(cur + start + i) = o;
        *(int4*)(deg + start + i) = z;   // ready for the next execution's hist
    }
}

// ---------------- fused work: scatter | movie_init(MMA) | gather_user ----------------
// scatter blocks scheduled FIRST: their L2-atomic stalls leave SM issue slots free for
// the tensor-core init and streaming gather blocks that share each wave, hiding the
// init/gather work inside scatter's ~51us atomic-bound window.
__global__ __launch_bounds__(256) void fused_work_kernel(
    const int4* __restrict__ src4, const int4* __restrict__ dst4,
    const float* __restrict__ movie_x, const float* __restrict__ lin_W,
    const float* __restrict__ lin_b,  const float* __restrict__ movie_emb,
    const int* __restrict__ movie_nid, __half* __restrict__ xm16,
    const float* __restrict__ user_emb, const int* __restrict__ user_nid,
    __half* __restrict__ xu16)
{
    int tid = threadIdx.x;

    if (blockIdx.x < HIST_BLOCKS) {
        // ---- scatter ----
        int i = blockIdx.x * 256 + tid;
        if (i >= N_EDGES / 4) return;
        int4 s = __ldg(src4 + i), d = __ldg(dst4 + i);
        g_csr_m[atomicAdd(&g_cur_m[d.x], 1)] = s.x;
        g_csr_u[atomicAdd(&g_cur_u[s.x], 1)] = d.x;
        g_csr_m[atomicAdd(&g_cur_m[d.y], 1)] = s.y;
        g_csr_u[atomicAdd(&g_cur_u[s.y], 1)] = d.y;
        g_csr_m[atomicAdd(&g_cur_m[d.z], 1)] = s.z;
        g_csr_u[atomicAdd(&g_cur_u[s.z], 1)] = d.z;
        g_csr_m[atomicAdd(&g_cur_m[d.w], 1)] = s.w;
        g_csr_u[atomicAdd(&g_cur_u[s.w], 1)] = d.w;
        return;
    }
    if (blockIdx.x >= HIST_BLOCKS + NB_M_CONST) {
        // ---- gather_user: x_user = user_emb[user_nid] (fp16) ----
        int i = (blockIdx.x - HIST_BLOCKS - NB_M_CONST) * 256 + tid;
        if (i >= N_USERS * 16) return;
        int r = i >> 4, c = i & 15;
        float4 v = __ldg((const float4*)user_emb + __ldg(user_nid + r) * 16 + c);
        __half2 h0 = __floats2half2_rn(v.x, v.y);
        __half2 h1 = __floats2half2_rn(v.z, v.w);
        uint2 o;
        o.x = *(unsigned int*)&h0;
        o.y = *(unsigned int*)&h1;
        ((uint2*)xu16)[i] = o;
        return;
    }

    // ---- movie_init via tensor cores, hi/lo fp16 split (3 MMAs, fp32-accurate) ----
    extern __shared__ char smem[];
    __half* Ah = (__half*)smem;                    // [128][A_STRIDE]
    __half* Al = Ah + 128 * A_STRIDE;              // [128][A_STRIDE]
    __half* Bh = Al + 128 * A_STRIDE;              // [64][A_STRIDE]
    __half* Bl = Bh + 64 * A_STRIDE;               // [64][A_STRIDE]
    float* bias_s = (float*)(Bl + 64 * A_STRIDE);  // [64]
    int* snid = (int*)(bias_s + 64);               // [128]

    const int n = N_MOVIES;
    int base = (blockIdx.x - HIST_BLOCKS) * 128;

    // stage A: 128 rows x 64 float2 = 8192 items
#pragma unroll
    for (int t = 0; t < 32; t++) {
        int idx = t * 256 + tid;
        int r = idx >> 6, p = idx & 63;
        float2 v = make_float2(0.f, 0.f);
        if (base + r < n)
            v = __ldg((const float2*)movie_x + (size_t)(base + r) * 64 + p);
        __half2 hi = __floats2half2_rn(v.x, v.y);
        float2 hf = __half22float2(hi);
        __half2 lo = __floats2half2_rn(v.x - hf.x, v.y - hf.y);
        *(__half2*)(Ah + r * A_STRIDE + 2 * p) = hi;
        *(__half2*)(Al + r * A_STRIDE + 2 * p) = lo;
    }
    // stage B: 64 j-rows x 64 float2 = 4096 items (lin_W is [64][128] row-major)
#pragma unroll
    for (int t = 0; t < 16; t++) {
        int idx = t * 256 + tid;
        int j = idx >> 6, p = idx & 63;
        float2 w = __ldg((const float2*)lin_W + j * 64 + p);
        __half2 hi = __floats2half2_rn(w.x, w.y);
        float2 hf = __half22float2(hi);
        __half2 lo = __floats2half2_rn(w.x - hf.x, w.y - hf.y);
        *(__half2*)(Bh + j * A_STRIDE + 2 * p) = hi;
        *(__half2*)(Bl + j * A_STRIDE + 2 * p) = lo;
    }
    if (tid < 64) bias_s[tid] = __ldg(lin_b + tid);
    if (tid < 128) {
        int r = base + tid;
        snid[tid] = __ldg(movie_nid + (r < n ? r : 0));
    }
    __syncthreads();

    int warp = tid >> 5, lane = tid & 31;
    int grp = lane >> 2, tig = lane & 3;
    int r0 = warp * 16;
    float acc[8][4];
#pragma unroll
    for (int nt = 0; nt < 8; nt++)
#pragma unroll
        for (int c = 0; c < 4; c++) acc[nt][c] = 0.f;

#pragma unroll
    for (int kt = 0; kt < 8; kt++) {
        int ar = r0 + grp, ac = kt * 16 + tig * 2;
        unsigned ah0 = *(const unsigned*)(Ah + ar * A_STRIDE + ac);
        unsigned ah1 = *(const unsigned*)(Ah + (ar + 8) * A_STRIDE + ac);
        unsigned ah2 = *(const unsigned*)(Ah + ar * A_STRIDE + ac + 8);
        unsigned ah3 = *(const unsigned*)(Ah + (ar + 8) * A_STRIDE + ac + 8);
        unsigned al0 = *(const unsigned*)(Al + ar * A_STRIDE + ac);
        unsigned al1 = *(const unsigned*)(Al + (ar + 8) * A_STRIDE + ac);
        unsigned al2 = *(const unsigned*)(Al + ar * A_STRIDE + ac + 8);
        unsigned al3 = *(const unsigned*)(Al + (ar + 8) * A_STRIDE + ac + 8);
#pragma unroll
        for (int nt = 0; nt < 8; nt++) {
            int bn = nt * 8 + grp, bk = kt * 16 + tig * 2;
            unsigned bh0 = *(const unsigned*)(Bh + bn * A_STRIDE + bk);
            unsigned bh1 = *(const unsigned*)(Bh + bn * A_STRIDE + bk + 8);
            unsigned bl0 = *(const unsigned*)(Bl + bn * A_STRIDE + bk);
            unsigned bl1 = *(const unsigned*)(Bl + bn * A_STRIDE + bk + 8);
            asm volatile(
                "mma.sync.aligned.m16n8k16.row.col.f32.f16.f16.f32 "
                "{%0,%1,%2,%3}, {%4,%5,%6,%7}, {%8,%9}, {%0,%1,%2,%3};"
                : "+f"(acc[nt][0]), "+f"(acc[nt][1]), "+f"(acc[nt][2]), "+f"(acc[nt][3])
                : "r"(ah0), "r"(ah1), "r"(ah2), "r"(ah3), "r"(bh0), "r"(bh1));
            asm volatile(
                "mma.sync.aligned.m16n8k16.row.col.f32.f16.f16.f32 "
                "{%0,%1,%2,%3}, {%4,%5,%6,%7}, {%8,%9}, {%0,%1,%2,%3};"
                : "+f"(acc[nt][0]), "+f"(acc[nt][1]), "+f"(acc[nt][2]), "+f"(acc[nt][3])
                : "r"(al0), "r"(al1), "r"(al2), "r"(al3), "r"(bh0), "r"(bh1));
            asm volatile(
                "mma.sync.aligned.m16n8k16.row.col.f32.f16.f16.f32 "
                "{%0,%1,%2,%3}, {%4,%5,%6,%7}, {%8,%9}, {%0,%1,%2,%3};"
                : "+f"(acc[nt][0]), "+f"(acc[nt][1]), "+f"(acc[nt][2]), "+f"(acc[nt][3])
                : "r"(ah0), "r"(ah1), "r"(ah2), "r"(ah3), "r"(bl0), "r"(bl1));
        }
    }

    // epilogue: + bias + movie_emb[nid] gather, fp16 out
#pragma unroll
    for (int nt = 0; nt < 8; nt++) {
        int col = nt * 8 + tig * 2;
        float bj0 = bias_s[col], bj1 = bias_s[col + 1];
        int lr0 = r0 + grp, lr1 = lr0 + 8;
        int gr0 = base + lr0, gr1 = base + lr1;
        if (gr0 < n) {
            float2 e = __ldg((const float2*)movie_emb + (size_t)snid[lr0] * 32 + col / 2);
            *(__half2*)(xm16 + (size_t)gr0 * 64 + col) =
                __floats2half2_rn(acc[nt][0] + bj0 + e.x, acc[nt][1] + bj1 + e.y);
        }
        if (gr1 < n) {
            float2 e = __ldg((const float2*)movie_emb + (size_t)snid[lr1] * 32 + col / 2);
            *(__half2*)(xm16 + (size_t)gr1 * 64 + col) =
                __floats2half2_rn(acc[nt][2] + bj0 + e.x, acc[nt][3] + bj1 + e.y);
        }
    }
}

// ---------------- segment mean, quarter-warp per node, fp16 depth-3 tree ----------------
// 8 lanes x uint4 (16B) = one 128B line per row. Tail indices select the permanent zero
// row, so feature loads are unconditional and MLP stays 8 through the tail. The 8 rows of
// a chunk are reduced fully in fp16 (depth-3 HADD2 tree: 7 adds/component), then ONE
// convert + packed-fp32 add per component per chunk.
__global__ __launch_bounds__(128) void aggregate2_kernel(
    const __half* __restrict__ src_for_m,  // user feats fp16
    const __half* __restrict__ src_for_u,  // movie feats fp16
    float* __restrict__ out_m, float* __restrict__ out_u)
{
    int q = (blockIdx.x * 128 + threadIdx.x) >> 3;
    int lane = threadIdx.x & 7;
    const uint4* xsrc; const int* csr; const int* off; float4* mean; int node, zrow;
    if (q < N_MOVIES) {
        node = q; xsrc = (const uint4*)src_for_m; csr = g_csr_m; off = g_off_m;
        mean = (float4*)out_m; zrow = N_USERS;
    } else {
        node = q - N_MOVIES;
        if (node >= N_USERS) return;
        xsrc = (const uint4*)src_for_u; csr = g_csr_u; off = g_off_u;
        mean = (float4*)out_u; zrow = N_MOVIES;
    }
    int s0 = __ldg(off + node);
    int deg = __ldg(off + node + 1) - s0;
    const int* nb = csr + s0;

    unsigned long long acc0 = 0, acc1 = 0, acc2 = 0, acc3 = 0;
    int nch = (deg + 7) >> 3;
    int idx[8];
#pragma unroll
    for (int k = 0; k < 8; k++)
        idx[k] = (k < deg) ? __ldg(nb + k) : zrow;
    for (int c = 0; c < nch; c++) {
        uint4 v[8];
#pragma unroll
        for (int k = 0; k < 8; k++)
            v[k] = __ldg(xsrc + (size_t)idx[k] * 8 + lane);
#pragma unroll
        for (int k = 0; k < 8; k++) {
            int i2 = (c + 1) * 8 + k;
            idx[k] = (i2 < deg) ? __ldg(nb + i2) : zrow;
        }
        // depth-3 fp16 tree per component: 8 rows -> 1 half2 (7 HADD2)
#pragma unroll
        for (int j = 0; j < 4; j++) {
            __half2 t0 = __hadd2(*(const __half2*)(&v[0].x + j), *(const __half2*)(&v[1].x + j));
            __half2 t1 = __hadd2(*(const __half2*)(&v[2].x + j), *(const __half2*)(&v[3].x + j));
            __half2 t2 = __hadd2(*(const __half2*)(&v[4].x + j), *(const __half2*)(&v[5].x + j));
            __half2 t3 = __hadd2(*(const __half2*)(&v[6].x + j), *(const __half2*)(&v[7].x + j));
            __half2 u0 = __hadd2(t0, t1);
            __half2 u1 = __hadd2(t2, t3);
            __half2 w  = __hadd2(u0, u1);
            float2 f = __half22float2(w);
            unsigned long long p = pack2(f.x, f.y);
            if (j == 0) acc0 = fadd2(acc0, p);
            else if (j == 1) acc1 = fadd2(acc1, p);
            else if (j == 2) acc2 = fadd2(acc2, p);
            else acc3 = fadd2(acc3, p);
        }
    }
    float f0, f1, f2, f3, f4, f5, f6, f7;
    unpack2(acc0, f0, f1); unpack2(acc1, f2, f3);
    unpack2(acc2, f4, f5); unpack2(acc3, f6, f7);
    float inv = deg > 0 ? 1.0f / (float)deg : 0.0f;   // deg==0 -> mean 0, matches reference
    float4 o0, o1;
    o0.x = f0 * inv; o0.y = f1 * inv; o0.z = f2 * inv; o0.w = f3 * inv;
    o1.x = f4 * inv; o1.y = f5 * inv; o1.z = f6 * inv; o1.w = f7 * inv;
    mean[(size_t)node * 16 + lane * 2] = o0;
    mean[(size_t)node * 16 + lane * 2 + 1] = o1;
}

// ---------------- SAGE transform via mma.sync m16n8k16 (fp16 in, fp32 accum) --------------
template<bool L1>
__global__ __launch_bounds__(256) void mma_transform_kernel(
    const float* __restrict__ mean_m, const __half* __restrict__ xd_m,
    const float* __restrict__ Wl_m, const float* __restrict__ bl_m,
    const float* __restrict__ Wr_m, __half* __restrict__ o16_m, float* __restrict__ o32_m,
    const float* __restrict__ mean_u, const __half* __restrict__ xd_u,
    const float* __restrict__ Wl_u, const float* __restrict__ bl_u,
    const float* __restrict__ Wr_u, __half* __restrict__ o16_u, float* __restrict__ o32_u,
    int nb_m)
{
    extern __shared__ char smem[];
    __half* As = (__half*)smem;                       // [128][A_STRIDE]
    __half* Bs = As + 128 * A_STRIDE;                 // [64][A_STRIDE]
    float* bias_s = (float*)(Bs + 64 * A_STRIDE);     // [64]

    const float *mean, *Wl, *bl, *Wr; const __half* xd; __half* o16; float* o32;
    int n, base;
    if ((int)blockIdx.x < nb_m) {
        mean = mean_m; xd = xd_m; Wl = Wl_m; bl = bl_m; Wr = Wr_m;
        o16 = o16_m; o32 = o32_m; n = N_MOVIES; base = blockIdx.x * 128;
    } else {
        mean = mean_u; xd = xd_u; Wl = Wl_u; bl = bl_u; Wr = Wr_u;
        o16 = o16_u; o32 = o32_u; n = N_USERS; base = (blockIdx.x - nb_m) * 128;
    }
    int tid = threadIdx.x;

    // stage B: 64 j-rows x 64 half2 pairs
#pragma unroll
    for (int t = 0; t < 16; t++) {
        int idx = t * 256 + tid;
        int j = idx >> 6, p = idx & 63;
        int k = 2 * p;
        float2 w;
        if (k < 64) w = __ldg((const float2*)(Wl + j * 64 + k));
        else        w = __ldg((const float2*)(Wr + j * 64 + (k - 64)));
        *(__half2*)(Bs + j * A_STRIDE + k) = __floats2half2_rn(w.x, w.y);
    }
    if (tid < 64) bias_s[tid] = __ldg(bl + tid);

    // stage A mean part: 128 rows x 32 half2 pairs (cols 0..63)
#pragma unroll
    for (int t = 0; t < 16; t++) {
        int idx = t * 256 + tid;
        int r = idx >> 5, p = idx & 31;
        __half2 h = __floats2half2_rn(0.f, 0.f);
        if (base + r < n) {
            float2 v = __ldg((const float2*)(mean + (size_t)(base + r) * 64 + 2 * p));
            h = __floats2half2_rn(v.x, v.y);
        }
        *(__half2*)(As + r * A_STRIDE + 2 * p) = h;
    }
    // stage A x part: 128 rows x 8 uint4 (cols 64..127, fp16 direct)
#pragma unroll
    for (int t = 0; t < 4; t++) {
        int idx = t * 256 + tid;
        int r = idx >> 3, q = idx & 7;
        uint4 u = make_uint4(0, 0, 0, 0);
        if (base + r < n)
            u = __ldg((const uint4*)(xd + (size_t)(base + r) * 64) + q);
        *(uint4*)(As + r * A_STRIDE + 64 + q * 8) = u;
    }
    __syncthreads();

    int warp = tid >> 5, lane = tid & 31;
    int grp = lane >> 2, tig = lane & 3;
    int r0 = warp * 16;
    float acc[8][4];
#pragma unroll
    for (int nt = 0; nt < 8; nt++)
#pragma unroll
        for (int c = 0; c < 4; c++) acc[nt][c] = 0.f;

#pragma unroll
    for (int kt = 0; kt < 8; kt++) {
        int ar = r0 + grp, ac = kt * 16 + tig * 2;
        unsigned a0 = *(const unsigned*)(As + ar * A_STRIDE + ac);
        unsigned a1 = *(const unsigned*)(As + (ar + 8) * A_STRIDE + ac);
        unsigned a2 = *(const unsigned*)(As + ar * A_STRIDE + ac + 8);
        unsigned a3 = *(const unsigned*)(As + (ar + 8) * A_STRIDE + ac + 8);
#pragma unroll
        for (int nt = 0; nt < 8; nt++) {
            int bn = nt * 8 + grp, bk = kt * 16 + tig * 2;
            unsigned b0 = *(const unsigned*)(Bs + bn * A_STRIDE + bk);
            unsigned b1 = *(const unsigned*)(Bs + bn * A_STRIDE + bk + 8);
            asm volatile(
                "mma.sync.aligned.m16n8k16.row.col.f32.f16.f16.f32 "
                "{%0,%1,%2,%3}, {%4,%5,%6,%7}, {%8,%9}, {%0,%1,%2,%3};"
                : "+f"(acc[nt][0]), "+f"(acc[nt][1]), "+f"(acc[nt][2]), "+f"(acc[nt][3])
                : "r"(a0), "r"(a1), "r"(a2), "r"(a3), "r"(b0), "r"(b1));
        }
    }

    // epilogue
#pragma unroll
    for (int nt = 0; nt < 8; nt++) {
        int col = nt * 8 + tig * 2;
        float bj0 = bias_s[col], bj1 = bias_s[col + 1];
        int gr0 = base + r0 + grp;
        int gr1 = gr0 + 8;
        float v00 = acc[nt][0] + bj0, v01 = acc[nt][1] + bj1;
        float v10 = acc[nt][2] + bj0, v11 = acc[nt][3] + bj1;
        if (L1) {
            v00 = fmaxf(v00, 0.f); v01 = fmaxf(v01, 0.f);
            v10 = fmaxf(v10, 0.f); v11 = fmaxf(v11, 0.f);
            if (gr0 < n) *(__half2*)(o16 + (size_t)gr0 * 64 + col) = __floats2half2_rn(v00, v01);
            if (gr1 < n) *(__half2*)(o16 + (size_t)gr1 * 64 + col) = __floats2half2_rn(v10, v11);
        } else {
            if (gr0 < n) *(float2*)(o32 + (size_t)gr0 * 64 + col) = make_float2(v00, v01);
            if (gr1 < n) *(float2*)(o32 + (size_t)gr1 * 64 + col) = make_float2(v10, v11);
        }
    }
}

// ---------------- dot-product decoder (half-warp per edge, fp32 inputs) ----------------
__global__ void decode_kernel(const float* __restrict__ ou, const float* __restrict__ om,
                              const int* __restrict__ ls, const int* __restrict__ ld,
                              float* __restrict__ out, int n)
{
    int e = (blockIdx.x * blockDim.x + threadIdx.x) >> 4;
    int lane = threadIdx.x & 15;
    if (e >= n) return;
    int u = __ldg(ls + e), m = __ldg(ld + e);
    float4 a = __ldg((const float4*)ou + (size_t)u * 16 + lane);
    float4 b = __ldg((const float4*)om + (size_t)m * 16 + lane);
    float p = a.x * b.x + a.y * b.y + a.z * b.z + a.w * b.w;
    p += __shfl_xor_sync(0xffffffffu, p, 1);
    p += __shfl_xor_sync(0xffffffffu, p, 2);
    p += __shfl_xor_sync(0xffffffffu, p, 4);
    p += __shfl_xor_sync(0xffffffffu, p, 8);
    if (lane == 0) out[e] = p;
}

// ---------------- launch ----------------
extern "C" void kernel_launch(void* const* d_in, const int* in_sizes, int n_in,
                              void* d_out, int out_size)
{
    const float* movie_x   = (const float*)d_in[0];
    const int*   user_nid  = (const int*)d_in[1];
    const int*   movie_nid = (const int*)d_in[2];
    const int*   e_src     = (const int*)d_in[3];
    const int*   e_dst     = (const int*)d_in[4];
    const int*   l_src     = (const int*)d_in[5];
    const int*   l_dst     = (const int*)d_in[6];
    const float* user_emb  = (const float*)d_in[7];
    const float* movie_emb = (const float*)d_in[8];
    const float* lin_W     = (const float*)d_in[9];
    const float* lin_b     = (const float*)d_in[10];
    const float* W_l_um1 = (const float*)d_in[11];
    const float* b_l_um1 = (const float*)d_in[12];
    const float* W_r_um1 = (const float*)d_in[13];
    const float* W_l_mu1 = (const float*)d_in[14];
    const float* b_l_mu1 = (const float*)d_in[15];
    const float* W_r_mu1 = (const float*)d_in[16];
    const float* W_l_um2 = (const float*)d_in[17];
    const float* b_l_um2 = (const float*)d_in[18];
    const float* W_r_um2 = (const float*)d_in[19];
    const float* W_l_mu2 = (const float*)d_in[20];
    const float* b_l_mu2 = (const float*)d_in[21];
    const float* W_r_mu2 = (const float*)d_in[22];
    float* out = (float*)d_out;

    float *mu, *mm;
    __half *x16u, *x16m, *h16u, *h16m;
    cudaGetSymbolAddress((void**)&mu, g_mu);
    cudaGetSymbolAddress((void**)&mm, g_mm);
    cudaGetSymbolAddress((void**)&x16u, g_x16u);
    cudaGetSymbolAddress((void**)&x16m, g_x16m);
    cudaGetSymbolAddress((void**)&h16u, g_h16u);
    cudaGetSymbolAddress((void**)&h16m, g_h16m);

    const int MMA_SMEM = (128 * A_STRIDE + 64 * A_STRIDE) * 2 + 64 * 4;  // 52480B
    const int MI_SMEM = (128 * A_STRIDE + 64 * A_STRIDE) * 2 * 2 + 64 * 4 + 128 * 4;
    cudaFuncSetAttribute(mma_transform_kernel<true>,
                         cudaFuncAttributeMaxDynamicSharedMemorySize, MMA_SMEM);
    cudaFuncSetAttribute(mma_transform_kernel<false>,
                         cudaFuncAttributeMaxDynamicSharedMemorySize, MMA_SMEM);
    cudaFuncSetAttribute(fused_work_kernel,
                         cudaFuncAttributeMaxDynamicSharedMemorySize, MI_SMEM);

    const int NB_M = NB_M_CONST;               // 391
    const int NB_U = (N_USERS + 127) / 128;    // 782

    // launch 0: hist standalone (full occupancy); g_deg_* arrive zeroed
    hist_kernel<<<HIST_BLOCKS, 256>>>((const int4*)e_src, (const int4*)e_dst);

    // launch 1: scan (writes off+cur, re-zeroes deg)
    scan_kernel<<<2, 1024>>>();

    // launch 2: fused scatter + movie_init(MMA) + gather_user (scatter blocks first)
    fused_work_kernel<<<HIST_BLOCKS + NB_M + GU_BLOCKS, 256, MI_SMEM>>>(
        (const int4*)e_src, (const int4*)e_dst,
        movie_x, lin_W, lin_b, movie_emb, movie_nid, x16m,
        user_emb, user_nid, x16u);

    const int AGG_BLOCKS = ((N_MOVIES + N_USERS) * 8 + 127) / 128;

    // launch 3 (profiled slot): layer-1 aggregate
    aggregate2_kernel<<<AGG_BLOCKS, 128>>>(x16u, x16m, mm, mu);
    mma_transform_kernel<true><<<NB_M + NB_U, 256, MMA_SMEM>>>(
        mm, x16m, W_l_um1, b_l_um1, W_r_um1, h16m, nullptr,
        mu, x16u, W_l_mu1, b_l_mu1, W_r_mu1, h16u, nullptr, NB_M);

    // layer 2 (no activation), fp32 outputs in-place over the mean buffers
    aggregate2_kernel<<<AGG_BLOCKS, 128>>>(h16u, h16m, mm, mu);
    mma_transform_kernel<false><<<NB_M + NB_U, 256, MMA_SMEM>>>(
        mm, h16m, W_l_um2, b_l_um2, W_r_um2, nullptr, mm,
        mu, h16u, W_l_mu2, b_l_mu2, W_r_mu2, nullptr, mu, NB_M);

    // decoder (fp32 finals: users in mu, movies in mm)
    decode_kernel<<<(N_LABEL * 16 + 255) / 256, 256>>>(mu, mm, l_src, l_dst, out, N_LABEL);
}

// round 16
// speedup vs baseline: 1.0583x; 1.0583x over previous
#include <cuda_runtime.h>
#include <cuda_fp16.h>

#define HIDDEN    64
#define N_USERS   100000
#define N_MOVIES  50000
#define MOVIE_FEAT 128
#define N_EDGES   2000000
#define N_LABEL   500000

// padded so the single-block scans can read int4 past n without guards
#define NM_PAD (N_MOVIES + 8192)
#define NU_PAD (N_USERS  + 8192)

// ---------------- device scratch (allocation-free rule: __device__ globals) ----------------
// g_deg_* are zero at module load and re-zeroed by scan_kernel after each consumption,
// so every execution of kernel_launch sees them zeroed.
__device__ __align__(16) int g_deg_m[NM_PAD];
__device__ __align__(16) int g_deg_u[NU_PAD];
__device__ __align__(16) int g_off_m[NM_PAD];
__device__ __align__(16) int g_off_u[NU_PAD];
__device__ __align__(16) int g_cur_m[NM_PAD];
__device__ __align__(16) int g_cur_u[NU_PAD];
__device__ int g_csr_m[N_EDGES];   // neighbors (user idx) of each movie, CSR by movie
__device__ int g_csr_u[N_EDGES];   // neighbors (movie idx) of each user, CSR by user
// fp16 node feature buffers with ONE extra row (index N) that is never written:
// __device__ globals are zero-initialized, every writer guards r < n, so row N is
// permanently zero -> aggregation tails load it unconditionally.
__device__ __align__(16) __half g_x16u[(N_USERS  + 1) * HIDDEN];
__device__ __align__(16) __half g_x16m[(N_MOVIES + 1) * HIDDEN];
__device__ __align__(16) __half g_h16u[(N_USERS  + 1) * HIDDEN];
__device__ __align__(16) __half g_h16m[(N_MOVIES + 1) * HIDDEN];
__device__ __align__(16) float g_mu[N_USERS  * HIDDEN];
__device__ __align__(16) float g_mm[N_MOVIES * HIDDEN];

// ---------------- packed f32x2 helpers ----------------
__device__ __forceinline__ unsigned long long pack2(float lo, float hi)
{
    unsigned long long r;
    asm("mov.b64 %0, {%1, %2};" : "=l"(r) : "f"(lo), "f"(hi));
    return r;
}
__device__ __forceinline__ void unpack2(unsigned long long v, float& lo, float& hi)
{
    asm("mov.b64 {%0, %1}, %2;" : "=f"(lo), "=f"(hi) : "l"(v));
}
__device__ __forceinline__ unsigned long long fadd2(unsigned long long a,
                                                    unsigned long long b)
{
    unsigned long long d;
    asm("add.rn.f32x2 %0, %1, %2;" : "=l"(d) : "l"(a), "l"(b));
    return d;
}

#define A_STRIDE 136   // halfs per MMA smem row (128 + 8 pad -> conflict-free frag loads)
#define NB_M_CONST ((N_MOVIES + 127) / 128)          // 391 movie-init blocks
#define GU_BLOCKS  ((N_USERS * 16 + 255) / 256)      // 6250 gather blocks
#define HIST_BLOCKS ((N_EDGES / 4 + 255) / 256)      // 1954 hist blocks

// ---------------- fused init: movie_init(MMA) | gather_user | hist ----------------
__global__ __launch_bounds__(256) void fused_init_kernel(
    const float* __restrict__ movie_x, const float* __restrict__ lin_W,
    const float* __restrict__ lin_b,  const float* __restrict__ movie_emb,
    const int* __restrict__ movie_nid, __half* __restrict__ xm16,
    const float* __restrict__ user_emb, const int* __restrict__ user_nid,
    __half* __restrict__ xu16,
    const int4* __restrict__ src4, const int4* __restrict__ dst4)
{
    int tid = threadIdx.x;

    if (blockIdx.x >= NB_M_CONST) {
        int b = blockIdx.x - NB_M_CONST;
        if (b < GU_BLOCKS) {
            // ---- gather_user: x_user = user_emb[user_nid] (fp16) ----
            int i = b * 256 + tid;
            if (i >= N_USERS * 16) return;
            int r = i >> 4, c = i & 15;
            float4 v = __ldg((const float4*)user_emb + __ldg(user_nid + r) * 16 + c);
            __half2 h0 = __floats2half2_rn(v.x, v.y);
            __half2 h1 = __floats2half2_rn(v.z, v.w);
            uint2 o;
            o.x = *(unsigned int*)&h0;
            o.y = *(unsigned int*)&h1;
            ((uint2*)xu16)[i] = o;
        } else {
            // ---- hist: degree histogram of both directions ----
            int i = (b - GU_BLOCKS) * 256 + tid;
            if (i >= N_EDGES / 4) return;
            int4 s = __ldg(src4 + i), d = __ldg(dst4 + i);
            atomicAdd(&g_deg_u[s.x], 1); atomicAdd(&g_deg_u[s.y], 1);
            atomicAdd(&g_deg_u[s.z], 1); atomicAdd(&g_deg_u[s.w], 1);
            atomicAdd(&g_deg_m[d.x], 1); atomicAdd(&g_deg_m[d.y], 1);
            atomicAdd(&g_deg_m[d.z], 1); atomicAdd(&g_deg_m[d.w], 1);
        }
        return;
    }

    // ---- movie_init via tensor cores, hi/lo fp16 split (3 MMAs, fp32-accurate) ----
    extern __shared__ char smem[];
    __half* Ah = (__half*)smem;                    // [128][A_STRIDE]
    __half* Al = Ah + 128 * A_STRIDE;              // [128][A_STRIDE]
    __half* Bh = Al + 128 * A_STRIDE;              // [64][A_STRIDE]
    __half* Bl = Bh + 64 * A_STRIDE;               // [64][A_STRIDE]
    float* bias_s = (float*)(Bl + 64 * A_STRIDE);  // [64]
    int* snid = (int*)(bias_s + 64);               // [128]

    const int n = N_MOVIES;
    int base = blockIdx.x * 128;

    // stage A: 128 rows x 64 float2 = 8192 items
#pragma unroll
    for (int t = 0; t < 32; t++) {
        int idx = t * 256 + tid;
        int r = idx >> 6, p = idx & 63;
        float2 v = make_float2(0.f, 0.f);
        if (base + r < n)
            v = __ldg((const float2*)movie_x + (size_t)(base + r) * 64 + p);
        __half2 hi = __floats2half2_rn(v.x, v.y);
        float2 hf = __half22float2(hi);
        __half2 lo = __floats2half2_rn(v.x - hf.x, v.y - hf.y);
        *(__half2*)(Ah + r * A_STRIDE + 2 * p) = hi;
        *(__half2*)(Al + r * A_STRIDE + 2 * p) = lo;
    }
    // stage B: 64 j-rows x 64 float2 = 4096 items (lin_W is [64][128] row-major)
#pragma unroll
    for (int t = 0; t < 16; t++) {
        int idx = t * 256 + tid;
        int j = idx >> 6, p = idx & 63;
        float2 w = __ldg((const float2*)lin_W + j * 64 + p);
        __half2 hi = __floats2half2_rn(w.x, w.y);
        float2 hf = __half22float2(hi);
        __half2 lo = __floats2half2_rn(w.x - hf.x, w.y - hf.y);
        *(__half2*)(Bh + j * A_STRIDE + 2 * p) = hi;
        *(__half2*)(Bl + j * A_STRIDE + 2 * p) = lo;
    }
    if (tid < 64) bias_s[tid] = __ldg(lin_b + tid);
    if (tid < 128) {
        int r = base + tid;
        snid[tid] = __ldg(movie_nid + (r < n ? r : 0));
    }
    __syncthreads();

    int warp = tid >> 5, lane = tid & 31;
    int grp = lane >> 2, tig = lane & 3;
    int r0 = warp * 16;
    float acc[8][4];
#pragma unroll
    for (int nt = 0; nt < 8; nt++)
#pragma unroll
        for (int c = 0; c < 4; c++) acc[nt][c] = 0.f;

#pragma unroll
    for (int kt = 0; kt < 8; kt++) {
        int ar = r0 + grp, ac = kt * 16 + tig * 2;
        unsigned ah0 = *(const unsigned*)(Ah + ar * A_STRIDE + ac);
        unsigned ah1 = *(const unsigned*)(Ah + (ar + 8) * A_STRIDE + ac);
        unsigned ah2 = *(const unsigned*)(Ah + ar * A_STRIDE + ac + 8);
        unsigned ah3 = *(const unsigned*)(Ah + (ar + 8) * A_STRIDE + ac + 8);
        unsigned al0 = *(const unsigned*)(Al + ar * A_STRIDE + ac);
        unsigned al1 = *(const unsigned*)(Al + (ar + 8) * A_STRIDE + ac);
        unsigned al2 = *(const unsigned*)(Al + ar * A_STRIDE + ac + 8);
        unsigned al3 = *(const unsigned*)(Al + (ar + 8) * A_STRIDE + ac + 8);
#pragma unroll
        for (int nt = 0; nt < 8; nt++) {
            int bn = nt * 8 + grp, bk = kt * 16 + tig * 2;
            unsigned bh0 = *(const unsigned*)(Bh + bn * A_STRIDE + bk);
            unsigned bh1 = *(const unsigned*)(Bh + bn * A_STRIDE + bk + 8);
            unsigned bl0 = *(const unsigned*)(Bl + bn * A_STRIDE + bk);
            unsigned bl1 = *(const unsigned*)(Bl + bn * A_STRIDE + bk + 8);
            asm volatile(
                "mma.sync.aligned.m16n8k16.row.col.f32.f16.f16.f32 "
                "{%0,%1,%2,%3}, {%4,%5,%6,%7}, {%8,%9}, {%0,%1,%2,%3};"
                : "+f"(acc[nt][0]), "+f"(acc[nt][1]), "+f"(acc[nt][2]), "+f"(acc[nt][3])
                : "r"(ah0), "r"(ah1), "r"(ah2), "r"(ah3), "r"(bh0), "r"(bh1));
            asm volatile(
                "mma.sync.aligned.m16n8k16.row.col.f32.f16.f16.f32 "
                "{%0,%1,%2,%3}, {%4,%5,%6,%7}, {%8,%9}, {%0,%1,%2,%3};"
                : "+f"(acc[nt][0]), "+f"(acc[nt][1]), "+f"(acc[nt][2]), "+f"(acc[nt][3])
                : "r"(al0), "r"(al1), "r"(al2), "r"(al3), "r"(bh0), "r"(bh1));
            asm volatile(
                "mma.sync.aligned.m16n8k16.row.col.f32.f16.f16.f32 "
                "{%0,%1,%2,%3}, {%4,%5,%6,%7}, {%8,%9}, {%0,%1,%2,%3};"
                : "+f"(acc[nt][0]), "+f"(acc[nt][1]), "+f"(acc[nt][2]), "+f"(acc[nt][3])
                : "r"(ah0), "r"(ah1), "r"(ah2), "r"(ah3), "r"(bl0), "r"(bl1));
        }
    }

    // epilogue: + bias + movie_emb[nid] gather, fp16 out
#pragma unroll
    for (int nt = 0; nt < 8; nt++) {
        int col = nt * 8 + tig * 2;
        float bj0 = bias_s[col], bj1 = bias_s[col + 1];
        int lr0 = r0 + grp, lr1 = lr0 + 8;
        int gr0 = base + lr0, gr1 = base + lr1;
        if (gr0 < n) {
            float2 e = __ldg((const float2*)movie_emb + (size_t)snid[lr0] * 32 + col / 2);
            *(__half2*)(xm16 + (size_t)gr0 * 64 + col) =
                __floats2half2_rn(acc[nt][0] + bj0 + e.x, acc[nt][1] + bj1 + e.y);
        }
        if (gr1 < n) {
            float2 e = __ldg((const float2*)movie_emb + (size_t)snid[lr1] * 32 + col / 2);
            *(__half2*)(xm16 + (size_t)gr1 * 64 + col) =
                __floats2half2_rn(acc[nt][2] + bj0 + e.x, acc[nt][3] + bj1 + e.y);
        }
    }
}

// block 0 scans movie degrees, block 1 scans user degrees; initializes cursors and
// re-zeroes the degree arrays (each thread zeroes its own chunk after reading it).
__global__ __launch_bounds__(1024) void scan_kernel()
{
    int n; int* deg; int* off; int* cur;
    if (blockIdx.x == 0) { n = N_MOVIES; deg = g_deg_m; off = g_off_m; cur = g_cur_m; }
    else                 { n = N_USERS;  deg = g_deg_u; off = g_off_u; cur = g_cur_u; }
    int chunk = ((((n + 1023) >> 10) + 3) & ~3);   // multiple of 4 for int4
    int t = threadIdx.x;
    int start = t * chunk;

    int s = 0;
    for (int i = 0; i < chunk; i += 4) {
        int4 v = *(const int4*)(deg + start + i);
        s += v.x + v.y + v.z + v.w;
    }
    __shared__ int sh[1024];
    sh[t] = s; __syncthreads();
    for (int d = 1; d < 1024; d <<= 1) {
        int v = (t >= d) ? sh[t - d] : 0;
        __syncthreads();
        sh[t] += v;
        __syncthreads();
    }
    int run = t ? sh[t - 1] : 0;
    int4 z = make_int4(0, 0, 0, 0);
    for (int i = 0; i < chunk; i += 4) {
        int4 v = *(const int4*)(deg + start + i);
        int4 o;
        o.x = run; run += v.x;
        o.y = run; run += v.y;
        o.z = run; run += v.z;
        o.w = run; run += v.w;
        *(int4*)(off + start + i) = o;
        *(int4*)(cur + start + i) = o;
        *(int4*)(deg + start + i) = z;   // ready for the next execution's hist
    }
}

__global__ void scatter_kernel(const int4* __restrict__ src4, const int4* __restrict__ dst4)
{
    int i = blockIdx.x * blockDim.x + threadIdx.x;
    if (i >= N_EDGES / 4) return;
    int4 s = __ldg(src4 + i), d = __ldg(dst4 + i);
    g_csr_m[atomicAdd(&g_cur_m[d.x], 1)] = s.x;
    g_csr_u[atomicAdd(&g_cur_u[s.x], 1)] = d.x;
    g_csr_m[atomicAdd(&g_cur_m[d.y], 1)] = s.y;
    g_csr_u[atomicAdd(&g_cur_u[s.y], 1)] = d.y;
    g_csr_m[atomicAdd(&g_cur_m[d.z], 1)] = s.z;
    g_csr_u[atomicAdd(&g_cur_u[s.z], 1)] = d.z;
    g_csr_m[atomicAdd(&g_cur_m[d.w], 1)] = s.w;
    g_csr_u[atomicAdd(&g_cur_u[s.w], 1)] = d.w;
}

// ---------------- segment mean, quarter-warp per node, fp16 depth-3 tree ----------------
// 8 lanes x uint4 (16B) = one 128B line per row. Tail indices select the permanent zero
// row, so feature loads are unconditional and MLP stays 8 through the tail. The 8 rows of
// a chunk are reduced fully in fp16 (depth-3 HADD2 tree: 7 adds/component), then ONE
// convert + packed-fp32 add per component per chunk.
__global__ __launch_bounds__(128) void aggregate2_kernel(
    const __half* __restrict__ src_for_m,  // user feats fp16
    const __half* __restrict__ src_for_u,  // movie feats fp16
    float* __restrict__ out_m, float* __restrict__ out_u)
{
    int q = (blockIdx.x * 128 + threadIdx.x) >> 3;
    int lane = threadIdx.x & 7;
    const uint4* xsrc; const int* csr; const int* off; float4* mean; int node, zrow;
    if (q < N_MOVIES) {
        node = q; xsrc = (const uint4*)src_for_m; csr = g_csr_m; off = g_off_m;
        mean = (float4*)out_m; zrow = N_USERS;
    } else {
        node = q - N_MOVIES;
        if (node >= N_USERS) return;
        xsrc = (const uint4*)src_for_u; csr = g_csr_u; off = g_off_u;
        mean = (float4*)out_u; zrow = N_MOVIES;
    }
    int s0 = __ldg(off + node);
    int deg = __ldg(off + node + 1) - s0;
    const int* nb = csr + s0;

    unsigned long long acc0 = 0, acc1 = 0, acc2 = 0, acc3 = 0;
    int nch = (deg + 7) >> 3;
    int idx[8];
#pragma unroll
    for (int k = 0; k < 8; k++)
        idx[k] = (k < deg) ? __ldg(nb + k) : zrow;
    for (int c = 0; c < nch; c++) {
        uint4 v[8];
#pragma unroll
        for (int k = 0; k < 8; k++)
            v[k] = __ldg(xsrc + (size_t)idx[k] * 8 + lane);
#pragma unroll
        for (int k = 0; k < 8; k++) {
            int i2 = (c + 1) * 8 + k;
            idx[k] = (i2 < deg) ? __ldg(nb + i2) : zrow;
        }
        // depth-3 fp16 tree per component: 8 rows -> 1 half2 (7 HADD2)
#pragma unroll
        for (int j = 0; j < 4; j++) {
            __half2 t0 = __hadd2(*(const __half2*)(&v[0].x + j), *(const __half2*)(&v[1].x + j));
            __half2 t1 = __hadd2(*(const __half2*)(&v[2].x + j), *(const __half2*)(&v[3].x + j));
            __half2 t2 = __hadd2(*(const __half2*)(&v[4].x + j), *(const __half2*)(&v[5].x + j));
            __half2 t3 = __hadd2(*(const __half2*)(&v[6].x + j), *(const __half2*)(&v[7].x + j));
            __half2 u0 = __hadd2(t0, t1);
            __half2 u1 = __hadd2(t2, t3);
            __half2 w  = __hadd2(u0, u1);
            float2 f = __half22float2(w);
            unsigned long long p = pack2(f.x, f.y);
            if (j == 0) acc0 = fadd2(acc0, p);
            else if (j == 1) acc1 = fadd2(acc1, p);
            else if (j == 2) acc2 = fadd2(acc2, p);
            else acc3 = fadd2(acc3, p);
        }
    }
    float f0, f1, f2, f3, f4, f5, f6, f7;
    unpack2(acc0, f0, f1); unpack2(acc1, f2, f3);
    unpack2(acc2, f4, f5); unpack2(acc3, f6, f7);
    float inv = deg > 0 ? 1.0f / (float)deg : 0.0f;   // deg==0 -> mean 0, matches reference
    float4 o0, o1;
    o0.x = f0 * inv; o0.y = f1 * inv; o0.z = f2 * inv; o0.w = f3 * inv;
    o1.x = f4 * inv; o1.y = f5 * inv; o1.z = f6 * inv; o1.w = f7 * inv;
    mean[(size_t)node * 16 + lane * 2] = o0;
    mean[(size_t)node * 16 + lane * 2 + 1] = o1;
}

// ---------------- SAGE transform via mma.sync m16n8k16 (fp16 in, fp32 accum) --------------
template<bool L1>
__global__ __launch_bounds__(256) void mma_transform_kernel(
    const float* __restrict__ mean_m, const __half* __restrict__ xd_m,
    const float* __restrict__ Wl_m, const float* __restrict__ bl_m,
    const float* __restrict__ Wr_m, __half* __restrict__ o16_m, float* __restrict__ o32_m,
    const float* __restrict__ mean_u, const __half* __restrict__ xd_u,
    const float* __restrict__ Wl_u, const float* __restrict__ bl_u,
    const float* __restrict__ Wr_u, __half* __restrict__ o16_u, float* __restrict__ o32_u,
    int nb_m)
{
    extern __shared__ char smem[];
    __half* As = (__half*)smem;                       // [128][A_STRIDE]
    __half* Bs = As + 128 * A_STRIDE;                 // [64][A_STRIDE]
    float* bias_s = (float*)(Bs + 64 * A_STRIDE);     // [64]

    const float *mean, *Wl, *bl, *Wr; const __half* xd; __half* o16; float* o32;
    int n, base;
    if ((int)blockIdx.x < nb_m) {
        mean = mean_m; xd = xd_m; Wl = Wl_m; bl = bl_m; Wr = Wr_m;
        o16 = o16_m; o32 = o32_m; n = N_MOVIES; base = blockIdx.x * 128;
    } else {
        mean = mean_u; xd = xd_u; Wl = Wl_u; bl = bl_u; Wr = Wr_u;
        o16 = o16_u; o32 = o32_u; n = N_USERS; base = (blockIdx.x - nb_m) * 128;
    }
    int tid = threadIdx.x;

    // stage B: 64 j-rows x 64 half2 pairs
#pragma unroll
    for (int t = 0; t < 16; t++) {
        int idx = t * 256 + tid;
        int j = idx >> 6, p = idx & 63;
        int k = 2 * p;
        float2 w;
        if (k < 64) w = __ldg((const float2*)(Wl + j * 64 + k));
        else        w = __ldg((const float2*)(Wr + j * 64 + (k - 64)));
        *(__half2*)(Bs + j * A_STRIDE + k) = __floats2half2_rn(w.x, w.y);
    }
    if (tid < 64) bias_s[tid] = __ldg(bl + tid);

    // stage A mean part: 128 rows x 32 half2 pairs (cols 0..63)
#pragma unroll
    for (int t = 0; t < 16; t++) {
        int idx = t * 256 + tid;
        int r = idx >> 5, p = idx & 31;
        __half2 h = __floats2half2_rn(0.f, 0.f);
        if (base + r < n) {
            float2 v = __ldg((const float2*)(mean + (size_t)(base + r) * 64 + 2 * p));
            h = __floats2half2_rn(v.x, v.y);
        }
        *(__half2*)(As + r * A_STRIDE + 2 * p) = h;
    }
    // stage A x part: 128 rows x 8 uint4 (cols 64..127, fp16 direct)
#pragma unroll
    for (int t = 0; t < 4; t++) {
        int idx = t * 256 + tid;
        int r = idx >> 3, q = idx & 7;
        uint4 u = make_uint4(0, 0, 0, 0);
        if (base + r < n)
            u = __ldg((const uint4*)(xd + (size_t)(base + r) * 64) + q);
        *(uint4*)(As + r * A_STRIDE + 64 + q * 8) = u;
    }
    __syncthreads();

    int warp = tid >> 5, lane = tid & 31;
    int grp = lane >> 2, tig = lane & 3;
    int r0 = warp * 16;
    float acc[8][4];
#pragma unroll
    for (int nt = 0; nt < 8; nt++)
#pragma unroll
        for (int c = 0; c < 4; c++) acc[nt][c] = 0.f;

#pragma unroll
    for (int kt = 0; kt < 8; kt++) {
        int ar = r0 + grp, ac = kt * 16 + tig * 2;
        unsigned a0 = *(const unsigned*)(As + ar * A_STRIDE + ac);
        unsigned a1 = *(const unsigned*)(As + (ar + 8) * A_STRIDE + ac);
        unsigned a2 = *(const unsigned*)(As + ar * A_STRIDE + ac + 8);
        unsigned a3 = *(const unsigned*)(As + (ar + 8) * A_STRIDE + ac + 8);
#pragma unroll
        for (int nt = 0; nt < 8; nt++) {
            int bn = nt * 8 + grp, bk = kt * 16 + tig * 2;
            unsigned b0 = *(const unsigned*)(Bs + bn * A_STRIDE + bk);
            unsigned b1 = *(const unsigned*)(Bs + bn * A_STRIDE + bk + 8);
            asm volatile(
                "mma.sync.aligned.m16n8k16.row.col.f32.f16.f16.f32 "
                "{%0,%1,%2,%3}, {%4,%5,%6,%7}, {%8,%9}, {%0,%1,%2,%3};"
                : "+f"(acc[nt][0]), "+f"(acc[nt][1]), "+f"(acc[nt][2]), "+f"(acc[nt][3])
                : "r"(a0), "r"(a1), "r"(a2), "r"(a3), "r"(b0), "r"(b1));
        }
    }

    // epilogue
#pragma unroll
    for (int nt = 0; nt < 8; nt++) {
        int col = nt * 8 + tig * 2;
        float bj0 = bias_s[col], bj1 = bias_s[col + 1];
        int gr0 = base + r0 + grp;
        int gr1 = gr0 + 8;
        float v00 = acc[nt][0] + bj0, v01 = acc[nt][1] + bj1;
        float v10 = acc[nt][2] + bj0, v11 = acc[nt][3] + bj1;
        if (L1) {
            v00 = fmaxf(v00, 0.f); v01 = fmaxf(v01, 0.f);
            v10 = fmaxf(v10, 0.f); v11 = fmaxf(v11, 0.f);
            if (gr0 < n) *(__half2*)(o16 + (size_t)gr0 * 64 + col) = __floats2half2_rn(v00, v01);
            if (gr1 < n) *(__half2*)(o16 + (size_t)gr1 * 64 + col) = __floats2half2_rn(v10, v11);
        } else {
            if (gr0 < n) *(float2*)(o32 + (size_t)gr0 * 64 + col) = make_float2(v00, v01);
            if (gr1 < n) *(float2*)(o32 + (size_t)gr1 * 64 + col) = make_float2(v10, v11);
        }
    }
}

// ---------------- dot-product decoder (half-warp per edge, fp32 inputs) ----------------
__global__ void decode_kernel(const float* __restrict__ ou, const float* __restrict__ om,
                              const int* __restrict__ ls, const int* __restrict__ ld,
                              float* __restrict__ out, int n)
{
    int e = (blockIdx.x * blockDim.x + threadIdx.x) >> 4;
    int lane = threadIdx.x & 15;
    if (e >= n) return;
    int u = __ldg(ls + e), m = __ldg(ld + e);
    float4 a = __ldg((const float4*)ou + (size_t)u * 16 + lane);
    float4 b = __ldg((const float4*)om + (size_t)m * 16 + lane);
    float p = a.x * b.x + a.y * b.y + a.z * b.z + a.w * b.w;
    p += __shfl_xor_sync(0xffffffffu, p, 1);
    p += __shfl_xor_sync(0xffffffffu, p, 2);
    p += __shfl_xor_sync(0xffffffffu, p, 4);
    p += __shfl_xor_sync(0xffffffffu, p, 8);
    if (lane == 0) out[e] = p;
}

// ---------------- launch ----------------
extern "C" void kernel_launch(void* const* d_in, const int* in_sizes, int n_in,
                              void* d_out, int out_size)
{
    const float* movie_x   = (const float*)d_in[0];
    const int*   user_nid  = (const int*)d_in[1];
    const int*   movie_nid = (const int*)d_in[2];
    const int*   e_src     = (const int*)d_in[3];
    const int*   e_dst     = (const int*)d_in[4];
    const int*   l_src     = (const int*)d_in[5];
    const int*   l_dst     = (const int*)d_in[6];
    const float* user_emb  = (const float*)d_in[7];
    const float* movie_emb = (const float*)d_in[8];
    const float* lin_W     = (const float*)d_in[9];
    const float* lin_b     = (const float*)d_in[10];
    const float* W_l_um1 = (const float*)d_in[11];
    const float* b_l_um1 = (const float*)d_in[12];
    const float* W_r_um1 = (const float*)d_in[13];
    const float* W_l_mu1 = (const float*)d_in[14];
    const float* b_l_mu1 = (const float*)d_in[15];
    const float* W_r_mu1 = (const float*)d_in[16];
    const float* W_l_um2 = (const float*)d_in[17];
    const float* b_l_um2 = (const float*)d_in[18];
    const float* W_r_um2 = (const float*)d_in[19];
    const float* W_l_mu2 = (const float*)d_in[20];
    const float* b_l_mu2 = (const float*)d_in[21];
    const float* W_r_mu2 = (const float*)d_in[22];
    float* out = (float*)d_out;

    float *mu, *mm;
    __half *x16u, *x16m, *h16u, *h16m;
    cudaGetSymbolAddress((void**)&mu, g_mu);
    cudaGetSymbolAddress((void**)&mm, g_mm);
    cudaGetSymbolAddress((void**)&x16u, g_x16u);
    cudaGetSymbolAddress((void**)&x16m, g_x16m);
    cudaGetSymbolAddress((void**)&h16u, g_h16u);
    cudaGetSymbolAddress((void**)&h16m, g_h16m);

    const int MMA_SMEM = (128 * A_STRIDE + 64 * A_STRIDE) * 2 + 64 * 4;  // 52480B
    const int MI_SMEM = (128 * A_STRIDE + 64 * A_STRIDE) * 2 * 2 + 64 * 4 + 128 * 4;
    cudaFuncSetAttribute(mma_transform_kernel<true>,
                         cudaFuncAttributeMaxDynamicSharedMemorySize, MMA_SMEM);
    cudaFuncSetAttribute(mma_transform_kernel<false>,
                         cudaFuncAttributeMaxDynamicSharedMemorySize, MMA_SMEM);
    cudaFuncSetAttribute(fused_init_kernel,
                         cudaFuncAttributeMaxDynamicSharedMemorySize, MI_SMEM);

    const int NB_M = NB_M_CONST;               // 391
    const int NB_U = (N_USERS + 127) / 128;    // 782

    // launch 0: fused movie_init(MMA) + gather_user + hist; g_deg_* arrive zeroed
    fused_init_kernel<<<NB_M + GU_BLOCKS + HIST_BLOCKS, 256, MI_SMEM>>>(
        movie_x, lin_W, lin_b, movie_emb, movie_nid, x16m,
        user_emb, user_nid, x16u,
        (const int4*)e_src, (const int4*)e_dst);

    // launch 1: scan (writes off+cur, re-zeroes deg)
    scan_kernel<<<2, 1024>>>();

    // launch 2: scatter
    scatter_kernel<<<HIST_BLOCKS, 256>>>((const int4*)e_src, (const int4*)e_dst);

    const int AGG_BLOCKS = ((N_MOVIES + N_USERS) * 8 + 127) / 128;

    // launch 3 (profiled slot): layer-1 aggregate
    aggregate2_kernel<<<AGG_BLOCKS, 128>>>(x16u, x16m, mm, mu);
    mma_transform_kernel<true><<<NB_M + NB_U, 256, MMA_SMEM>>>(
        mm, x16m, W_l_um1, b_l_um1, W_r_um1, h16m, nullptr,
        mu, x16u, W_l_mu1, b_l_mu1, W_r_mu1, h16u, nullptr, NB_M);

    // layer 2 (no activation), fp32 outputs in-place over the mean buffers
    aggregate2_kernel<<<AGG_BLOCKS, 128>>>(h16u, h16m, mm, mu);
    mma_transform_kernel<false><<<NB_M + NB_U, 256, MMA_SMEM>>>(
        mm, h16m, W_l_um2, b_l_um2, W_r_um2, nullptr, mm,
        mu, h16u, W_l_mu2, b_l_mu2, W_r_mu2, nullptr, mu, NB_M);

    // decoder (fp32 finals: users in mu, movies in mm)
    decode_kernel<<<(N_LABEL * 16 + 255) / 256, 256>>>(mu, mm, l_src, l_dst, out, N_LABEL);
}